// round 17
// baseline (speedup 1.0000x reference)
#include <cuda_runtime.h>
#include <cuda_bf16.h>
#include <cstdint>

#define BB    16
#define NPTS  4096
#define MQ    1024
#define KNB   32
#define S_TOTAL (BB*MQ*KNB)
#define FULLM 0xffffffffu

typedef unsigned long long ull;

// ---------------- device scratch -------------------------------------------
__device__ __align__(16) int   g_idx[S_TOTAL];
__device__ __align__(16) float g_featT[BB*NPTS*64];
__device__ __align__(16) float g_y1[(size_t)S_TOTAL*64];
__device__ __align__(16) float g_y2[(size_t)S_TOTAL*64];
__device__ __align__(16) float g_ymax[BB*MQ*128];
__device__ __align__(16) float g_ymin[BB*MQ*128];
__device__ __align__(16) float g_psum[128*8192];
__device__ __align__(16) float g_psq [128*8192];
__device__ __align__(16) float g_aff[3][256];

// ---------------- mma helpers ----------------------------------------------
__device__ __forceinline__ void ldm4(uint32_t* r, uint32_t addr) {
    asm volatile("ldmatrix.sync.aligned.m8n8.x4.shared.b16 {%0,%1,%2,%3}, [%4];"
        : "=r"(r[0]), "=r"(r[1]), "=r"(r[2]), "=r"(r[3]) : "r"(addr));
}
__device__ __forceinline__ void mma_bf16(float* d, const uint32_t* a,
                                         uint32_t b0, uint32_t b1) {
    asm volatile("mma.sync.aligned.m16n8k16.row.col.f32.bf16.bf16.f32 "
        "{%0,%1,%2,%3}, {%4,%5,%6,%7}, {%8,%9}, {%0,%1,%2,%3};"
        : "+f"(d[0]), "+f"(d[1]), "+f"(d[2]), "+f"(d[3])
        : "r"(a[0]), "r"(a[1]), "r"(a[2]), "r"(a[3]), "r"(b0), "r"(b1));
}
__device__ __forceinline__ void mk2(float x, float y, uint32_t& h, uint32_t& l) {
    __nv_bfloat162 hh = __floats2bfloat162_rn(x, y);
    h = *(uint32_t*)&hh;
    __nv_bfloat162 ll = __floats2bfloat162_rn(x - __low2float(hh), y - __high2float(hh));
    l = *(uint32_t*)&ll;
}

// ---------------- KNN + features transpose fused ---------------------------
__global__ __launch_bounds__(512) void knnT_kernel(const float* __restrict__ loc,
                                                   const float* __restrict__ newloc,
                                                   const float* __restrict__ feats,
                                                   float* __restrict__ featT,
                                                   int* __restrict__ idxout)
{
    extern __shared__ __align__(16) char smc[];
    float*  smem  = (float*)smc;
    float4* sloc4 = (float4*)smc;
    int b = blockIdx.x >> 4;
    int grp = blockIdx.x & 15;
    int tid = threadIdx.x;

    for (int h = 0; h < 2; h++) {
        int n0 = grp * 256 + h * 128;
        for (int i = tid; i < 64 * 128; i += 512) {
            int c = i >> 7, n = i & 127;
            smem[n * 65 + c] = feats[((size_t)b * 64 + c) * NPTS + n0 + n];
        }
        __syncthreads();
        for (int i = tid; i < 64 * 128; i += 512) {
            int n = i >> 6, c = i & 63;
            featT[((size_t)b * NPTS + n0 + n) * 64 + c] = smem[n * 65 + c];
        }
        __syncthreads();
    }

    for (int i = tid; i < NPTS; i += 512) {
        const float* p = loc + ((size_t)b * NPTS + i) * 3;
        float x = p[0], y = p[1], z = p[2];
        sloc4[i] = make_float4(x, y, z, x * x + y * y + z * z);
    }
    __syncthreads();

    int warp = tid >> 5, lane = tid & 31;
    for (int j = 0; j < 4; j++) {
        int m = grp * 64 + j * 16 + warp;
        const float* q = newloc + ((size_t)b * MQ + m) * 3;
        float qx = q[0], qy = q[1], qz = q[2];
        float q2 = qx * qx + qy * qy + qz * qz;

        float v1 = 3.4e38f, v2 = 3.4e38f;
        int   i1 = -1, i2 = -1;
#pragma unroll 4
        for (int it = 0; it < 128; it++) {
            int p = it * 32 + lane;
            float4 P = sloc4[p];
            float dot = qx * P.x + qy * P.y + qz * P.z;
            float d2 = (q2 + P.w) - 2.0f * dot;
            if (d2 < v2) {
                if (d2 < v1) { v2 = v1; i2 = i1; v1 = d2; i1 = p; }
                else         { v2 = d2; i2 = p; }
            }
        }

        float va = v1, vb = v2; int ia = i1, ib = i2;
#pragma unroll
        for (int k = 2; k <= 32; k <<= 1) {
#pragma unroll
            for (int jj = k >> 1; jj; jj >>= 1) {
                bool keep = ((lane & jj) == 0) == ((lane & k) == 0);
                float ov = __shfl_xor_sync(FULLM, va, jj);
                int   oi = __shfl_xor_sync(FULLM, ia, jj);
                bool lt = (va < ov) || (va == ov && ia < oi);
                bool sel = (keep == lt);
                va = sel ? va : ov;  ia = sel ? ia : oi;
                float ow = __shfl_xor_sync(FULLM, vb, jj);
                int   oj = __shfl_xor_sync(FULLM, ib, jj);
                bool lt2 = (vb < ow) || (vb == ow && ib < oj);
                bool sel2 = (keep == lt2);
                vb = sel2 ? vb : ow;  ib = sel2 ? ib : oj;
            }
        }
        float brv = __shfl_sync(FULLM, vb, 31 - lane);
        int   bri = __shfl_sync(FULLM, ib, 31 - lane);
        bool ltab = (va < brv) || (va == brv && ia < bri);
        float Cf = ltab ? va : brv;
        int   Ci = ltab ? ia : bri;
#pragma unroll
        for (int jj = 16; jj; jj >>= 1) {
            bool lower = (lane & jj) == 0;
            float ov = __shfl_xor_sync(FULLM, Cf, jj);
            int   oi = __shfl_xor_sync(FULLM, Ci, jj);
            bool lt = (Cf < ov) || (Cf == ov && Ci < oi);
            bool sel = (lower == lt);
            Cf = sel ? Cf : ov;  Ci = sel ? Ci : oi;
        }
        float Tpd = __shfl_sync(FULLM, Cf, 31);
        int   Tpi = __shfl_sync(FULLM, Ci, 31);

#pragma unroll 4
        for (int it = 0; it < 128; it++) {
            int p = it * 32 + lane;
            float4 P = sloc4[p];
            float dot = qx * P.x + qy * P.y + qz * P.z;
            float d2 = (q2 + P.w) - 2.0f * dot;
            bool inb = (d2 < Tpd) || (d2 == Tpd && p < Tpi);
            bool miss = inb && (p != i1) && (p != i2);
            unsigned bm = __ballot_sync(FULLM, miss);
            while (bm) {
                int src = __ffs(bm) - 1; bm &= bm - 1;
                float nf = __shfl_sync(FULLM, d2, src);
                int   ni = it * 32 + src;
                int pos = __popc(__ballot_sync(FULLM, (Cf < nf) || (Cf == nf && Ci < ni)));
                float pf = __shfl_up_sync(FULLM, Cf, 1);
                int   pi = __shfl_up_sync(FULLM, Ci, 1);
                if (lane == pos)      { Cf = nf; Ci = ni; }
                else if (lane > pos)  { Cf = pf; Ci = pi; }
            }
        }
        idxout[((size_t)b * MQ + m) * KNB + lane] = Ci;
    }
}

// ---------------- tensor-core GEMM stage, register-direct A ----------------
// All stages: SPB=128 samples/CTA, warp tile MT=2 x NT=8.
// STAGE 1/2: 128 thr, 4 warps = 4 row groups, all 64 couts.
// STAGE 3:   256 thr, 8 warps = 4 row groups x 2 cout halves; fused k-max/min.
template<int STAGE>
__global__ __launch_bounds__((STAGE == 3) ? 256 : 128, (STAGE == 3) ? 2 : 4)
void gemm_mma(
    const float* __restrict__ W, const float* __restrict__ src,
    const float* __restrict__ aff, float* __restrict__ yout,
    float* __restrict__ ymax, float* __restrict__ ymin,
    float* __restrict__ psum, float* __restrict__ psq,
    const int* __restrict__ idx, const float* __restrict__ loc,
    const float* __restrict__ newloc, const float* __restrict__ featT)
{
    constexpr int COUT = (STAGE == 3) ? 128 : 64;
    constexpr int THREADS = (STAGE == 3) ? 256 : 128;
    constexpr int NW = THREADS / 32;
    constexpr int WBYT = COUT * 72 * 2;

    extern __shared__ __align__(16) char smg[];
    __nv_bfloat16* Wh = (__nv_bfloat16*)smg;
    __nv_bfloat16* Wl = (__nv_bfloat16*)(smg + WBYT);
    float* afs  = (float*)(smg + 2 * WBYT);   // [a(64) | c(64)]
    float* wloc = afs + 128;                  // 64*4 (stage1)
    float* sps  = wloc + 256;                 // NW*64
    float* spq  = sps + NW * 64;              // NW*64

    int tid = threadIdx.x, warp = tid >> 5, lane = tid & 31;
    int blk = blockIdx.x;
    int sbase = blk * 128;
    int r = lane >> 2, cg = lane & 3, c2 = cg * 2;
    int wr = (STAGE == 3) ? (warp & 3) : warp;
    int wc = (STAGE == 3) ? (warp >> 2) : 0;
    int wb = wr * 32;
    int cb = wc * 64;

    if (STAGE > 1 && tid < 128)
        afs[tid] = (tid < 64) ? aff[tid] : aff[128 + tid - 64];

    for (int i = tid; i < COUT * 64; i += THREADS) {
        int co = i >> 6, k = i & 63;
        float v = (STAGE == 1) ? W[co * 67 + 3 + k] : W[co * 64 + k];
        __nv_bfloat16 h = __float2bfloat16(v);
        Wh[co * 72 + k] = h;
        Wl[co * 72 + k] = __float2bfloat16(v - __bfloat162float(h));
    }
    if (STAGE == 1)
        for (int i = tid; i < 192; i += THREADS) {
            int co = i / 3, c = i - co * 3;
            wloc[co * 4 + c] = W[co * 67 + c];
        }
    __syncthreads();

    const float* row0[2];
    const float* row1[2];
    float acc[2][8][4];
#pragma unroll
    for (int t = 0; t < 2; t++) {
        int s0 = sbase + wb + t * 16 + r;
        int s1 = s0 + 8;
        if (STAGE == 1) {
            int n0 = idx[s0], n1 = idx[s1];
            int b = s0 >> 15;
            row0[t] = featT + (size_t)(b * NPTS + n0) * 64;
            row1[t] = featT + (size_t)(b * NPTS + n1) * 64;
            const float* lp0 = loc + (size_t)(b * NPTS + n0) * 3;
            const float* lp1 = loc + (size_t)(b * NPTS + n1) * 3;
            const float* qp0 = newloc + (size_t)(b * MQ + ((s0 >> 5) & (MQ - 1))) * 3;
            const float* qp1 = newloc + (size_t)(b * MQ + ((s1 >> 5) & (MQ - 1))) * 3;
            float rx0 = lp0[0] - qp0[0], ry0 = lp0[1] - qp0[1], rz0 = lp0[2] - qp0[2];
            float rx1 = lp1[0] - qp1[0], ry1 = lp1[1] - qp1[1], rz1 = lp1[2] - qp1[2];
#pragma unroll
            for (int n = 0; n < 8; n++)
#pragma unroll
                for (int cc = 0; cc < 2; cc++) {
                    const float* wl = wloc + (n * 8 + c2 + cc) * 4;
                    acc[t][n][cc]     = rx0 * wl[0] + ry0 * wl[1] + rz0 * wl[2];
                    acc[t][n][2 + cc] = rx1 * wl[0] + ry1 * wl[1] + rz1 * wl[2];
                }
        } else {
            row0[t] = src + (size_t)s0 * 64;
            row1[t] = src + (size_t)s1 * 64;
#pragma unroll
            for (int n = 0; n < 8; n++)
#pragma unroll
                for (int p = 0; p < 4; p++) acc[t][n][p] = 0.f;
        }
    }

    uint32_t aWh = (uint32_t)__cvta_generic_to_shared(Wh);
    uint32_t aWl = (uint32_t)__cvta_generic_to_shared(Wl);

#pragma unroll
    for (int k = 0; k < 4; k++) {
        int c0 = c2 + k * 16;
        uint32_t ah[2][4], al[2][4];
#pragma unroll
        for (int t = 0; t < 2; t++) {
            float2 u00 = *(const float2*)(row0[t] + c0);
            float2 u08 = *(const float2*)(row0[t] + c0 + 8);
            float2 u10 = *(const float2*)(row1[t] + c0);
            float2 u18 = *(const float2*)(row1[t] + c0 + 8);
            if (STAGE > 1) {
                float2 a0 = *(const float2*)(afs + c0);
                float2 cc0 = *(const float2*)(afs + 64 + c0);
                float2 a8 = *(const float2*)(afs + c0 + 8);
                float2 cc8 = *(const float2*)(afs + 64 + c0 + 8);
                u00.x = fmaxf(0.f, fmaf(a0.x, u00.x, cc0.x));
                u00.y = fmaxf(0.f, fmaf(a0.y, u00.y, cc0.y));
                u08.x = fmaxf(0.f, fmaf(a8.x, u08.x, cc8.x));
                u08.y = fmaxf(0.f, fmaf(a8.y, u08.y, cc8.y));
                u10.x = fmaxf(0.f, fmaf(a0.x, u10.x, cc0.x));
                u10.y = fmaxf(0.f, fmaf(a0.y, u10.y, cc0.y));
                u18.x = fmaxf(0.f, fmaf(a8.x, u18.x, cc8.x));
                u18.y = fmaxf(0.f, fmaf(a8.y, u18.y, cc8.y));
            }
            mk2(u00.x, u00.y, ah[t][0], al[t][0]);
            mk2(u10.x, u10.y, ah[t][1], al[t][1]);
            mk2(u08.x, u08.y, ah[t][2], al[t][2]);
            mk2(u18.x, u18.y, ah[t][3], al[t][3]);
        }
#pragma unroll
        for (int p = 0; p < 4; p++) {
            uint32_t bo = (cb + p * 16 + (lane & 7) + ((lane >> 4) & 1) * 8) * 144
                        + k * 32 + ((lane >> 3) & 1) * 16;
            uint32_t bh[4], bl[4];
            ldm4(bh, aWh + bo);
            ldm4(bl, aWl + bo);
#pragma unroll
            for (int t = 0; t < 2; t++) {
                mma_bf16(acc[t][2 * p],     ah[t], bh[0], bh[1]);
                mma_bf16(acc[t][2 * p],     ah[t], bl[0], bl[1]);
                mma_bf16(acc[t][2 * p],     al[t], bh[0], bh[1]);
                mma_bf16(acc[t][2 * p + 1], ah[t], bh[2], bh[3]);
                mma_bf16(acc[t][2 * p + 1], ah[t], bl[2], bl[3]);
                mma_bf16(acc[t][2 * p + 1], al[t], bh[2], bh[3]);
            }
        }
    }

    // epilogue: y store (stage1/2), BN partials, stage3 per-warp k-max/min
#pragma unroll
    for (int n = 0; n < 8; n++) {
        float ps0 = 0.f, ps1 = 0.f, pq0 = 0.f, pq1 = 0.f;
        float mx0 = -3.4e38f, mx1 = -3.4e38f, mn0 = 3.4e38f, mn1 = 3.4e38f;
#pragma unroll
        for (int t = 0; t < 2; t++) {
            float d0 = acc[t][n][0], d1 = acc[t][n][1];
            float d2 = acc[t][n][2], d3 = acc[t][n][3];
            if (STAGE < 3) {
                int row = sbase + wb + t * 16 + r;
                *(float2*)(yout + (size_t)row * 64 + n * 8 + c2) = make_float2(d0, d1);
                *(float2*)(yout + (size_t)(row + 8) * 64 + n * 8 + c2) = make_float2(d2, d3);
            }
            ps0 += d0 + d2; ps1 += d1 + d3;
            pq0 += d0 * d0 + d2 * d2; pq1 += d1 * d1 + d3 * d3;
            if (STAGE == 3) {
                mx0 = fmaxf(mx0, fmaxf(d0, d2)); mx1 = fmaxf(mx1, fmaxf(d1, d3));
                mn0 = fminf(mn0, fminf(d0, d2)); mn1 = fminf(mn1, fminf(d1, d3));
            }
        }
#pragma unroll
        for (int off = 4; off <= 16; off <<= 1) {
            ps0 += __shfl_xor_sync(FULLM, ps0, off);
            ps1 += __shfl_xor_sync(FULLM, ps1, off);
            pq0 += __shfl_xor_sync(FULLM, pq0, off);
            pq1 += __shfl_xor_sync(FULLM, pq1, off);
            if (STAGE == 3) {
                mx0 = fmaxf(mx0, __shfl_xor_sync(FULLM, mx0, off));
                mx1 = fmaxf(mx1, __shfl_xor_sync(FULLM, mx1, off));
                mn0 = fminf(mn0, __shfl_xor_sync(FULLM, mn0, off));
                mn1 = fminf(mn1, __shfl_xor_sync(FULLM, mn1, off));
            }
        }
        if (lane < 4) {
            int l = n * 8 + c2;
            sps[warp * 64 + l] = ps0;  sps[warp * 64 + l + 1] = ps1;
            spq[warp * 64 + l] = pq0;  spq[warp * 64 + l + 1] = pq1;
            if (STAGE == 3) {
                int m = blk * 4 + wr;
                *(float2*)(ymax + (size_t)m * 128 + cb + l) = make_float2(mx0, mx1);
                *(float2*)(ymin + (size_t)m * 128 + cb + l) = make_float2(mn0, mn1);
            }
        }
    }
    __syncthreads();
    for (int ch = tid; ch < COUT; ch += THREADS) {
        int wcc = ch >> 6, l = ch & 63;
        float a = sps[(wcc * 4 + 0) * 64 + l] + sps[(wcc * 4 + 1) * 64 + l]
                + sps[(wcc * 4 + 2) * 64 + l] + sps[(wcc * 4 + 3) * 64 + l];
        float q = spq[(wcc * 4 + 0) * 64 + l] + spq[(wcc * 4 + 1) * 64 + l]
                + spq[(wcc * 4 + 2) * 64 + l] + spq[(wcc * 4 + 3) * 64 + l];
        psum[(size_t)ch * 8192 + blk] = a;
        psq [(size_t)ch * 8192 + blk] = q;
    }
}

// ---------------- BN finalize ----------------------------------------------
__global__ void bn_finalize(const float* __restrict__ psum, const float* __restrict__ psq,
                            const float* __restrict__ g, const float* __restrict__ beta,
                            float* __restrict__ aff, int NB)
{
    int ch = blockIdx.x, tid = threadIdx.x;
    __shared__ float s1[256], s2[256];
    float a = 0.f, q = 0.f;
    for (int i = tid; i < NB; i += 256) {
        a += psum[(size_t)ch * 8192 + i];
        q += psq [(size_t)ch * 8192 + i];
    }
    s1[tid] = a; s2[tid] = q; __syncthreads();
    for (int st = 128; st > 0; st >>= 1) {
        if (tid < st) { s1[tid] += s1[tid + st]; s2[tid] += s2[tid + st]; }
        __syncthreads();
    }
    if (tid == 0) {
        const float invS = 1.0f / (float)S_TOTAL;
        float mu = s1[0] * invS;
        float var = s2[0] * invS - mu * mu;
        float rs = rsqrtf(var + 1e-5f);
        float aa = g[ch] * rs;
        aff[ch] = aa;
        aff[128 + ch] = beta[ch] - mu * aa;
    }
}

// ---------------- final: affine3 + relu on k-extremum, transpose -----------
__global__ __launch_bounds__(256) void final_kernel(const float* __restrict__ ymax,
                                                    const float* __restrict__ ymin,
                                                    const float* __restrict__ aff,
                                                    float* __restrict__ out)
{
    __shared__ float t[128 * 65];
    int b = blockIdx.x >> 4;
    int mg = blockIdx.x & 15;
    int tid = threadIdx.x;
    for (int i = tid; i < 8192; i += 256) {
        int m = i >> 7, ch = i & 127;
        float a = aff[ch], cc = aff[128 + ch];
        size_t base = ((size_t)(b * MQ + mg * 64 + m)) * 128 + ch;
        float val = (a > 0.f) ? ymax[base] : ymin[base];
        t[ch * 65 + m] = fmaxf(0.f, fmaf(a, val, cc));
    }
    __syncthreads();
    for (int i = tid; i < 8192; i += 256) {
        int ch = i >> 6, m = i & 63;
        out[((size_t)(b * 128 + ch)) * MQ + mg * 64 + m] = t[ch * 65 + m];
    }
}

// ---------------- launch ----------------------------------------------------
extern "C" void kernel_launch(void* const* d_in, const int* in_sizes, int n_in,
                              void* d_out, int out_size)
{
    const float* loc    = (const float*)d_in[0];
    const float* newloc = (const float*)d_in[1];
    const float* feats  = (const float*)d_in[2];
    const float* W1 = (const float*)d_in[3];
    const float* g1 = (const float*)d_in[4];
    const float* b1 = (const float*)d_in[5];
    const float* W2 = (const float*)d_in[6];
    const float* g2 = (const float*)d_in[7];
    const float* b2 = (const float*)d_in[8];
    const float* W3 = (const float*)d_in[9];
    const float* g3 = (const float*)d_in[10];
    const float* b3 = (const float*)d_in[11];
    float* out = (float*)d_out;

    int*   idx   = nullptr;  cudaGetSymbolAddress((void**)&idx,   g_idx);
    float* featT = nullptr;  cudaGetSymbolAddress((void**)&featT, g_featT);
    float* y1    = nullptr;  cudaGetSymbolAddress((void**)&y1,    g_y1);
    float* y2    = nullptr;  cudaGetSymbolAddress((void**)&y2,    g_y2);
    float* ymax  = nullptr;  cudaGetSymbolAddress((void**)&ymax,  g_ymax);
    float* ymin  = nullptr;  cudaGetSymbolAddress((void**)&ymin,  g_ymin);
    float* psum  = nullptr;  cudaGetSymbolAddress((void**)&psum,  g_psum);
    float* psq   = nullptr;  cudaGetSymbolAddress((void**)&psq,   g_psq);
    float* aff   = nullptr;  cudaGetSymbolAddress((void**)&aff,   g_aff);

    // smem: 2*W tile + [afs 128 | wloc 256 | sps NW*64 | spq NW*64]
    const int SM12 = 2 * (64 * 144)  + (128 + 256 + 4 * 64 + 4 * 64) * 4;   // 21504
    const int SM3  = 2 * (128 * 144) + (128 + 256 + 8 * 64 + 8 * 64) * 4;   // 42496
    cudaFuncSetAttribute(knnT_kernel, cudaFuncAttributeMaxDynamicSharedMemorySize, 65536);

    knnT_kernel<<<256, 512, 65536>>>(loc, newloc, feats, featT, idx);

    gemm_mma<1><<<4096, 128, SM12>>>(W1, nullptr, nullptr, y1, nullptr, nullptr,
                                     psum, psq, idx, loc, newloc, featT);
    bn_finalize<<<64, 256>>>(psum, psq, g1, b1, aff + 0 * 256, 4096);

    gemm_mma<2><<<4096, 128, SM12>>>(W2, y1, aff + 0 * 256, y2, nullptr, nullptr,
                                     psum, psq, idx, loc, newloc, featT);
    bn_finalize<<<64, 256>>>(psum, psq, g2, b2, aff + 1 * 256, 4096);

    gemm_mma<3><<<4096, 256, SM3>>>(W3, y2, aff + 1 * 256, nullptr, ymax, ymin,
                                    psum, psq, idx, loc, newloc, featT);
    bn_finalize<<<128, 256>>>(psum, psq, g3, b3, aff + 2 * 256, 4096);

    final_kernel<<<BB * 16, 256>>>(ymax, ymin, aff + 2 * 256, out);
    (void)in_sizes; (void)n_in; (void)out_size;
}